// round 7
// baseline (speedup 1.0000x reference)
#include <cuda_runtime.h>
#include <math.h>

// Problem constants: N=100000, E=1600000, F_IN=256, F_OUT=40
#define N_MAX 100000
#define E_MAX 1600000
#define F_IN  256
#define F_OUT 40
#define F4    (F_OUT / 4)   // 10 float4 chunks per node row
#define SCAN_BS 1024
#define SCAN_NB ((N_MAX + SCAN_BS - 1) / SCAN_BS)   // 98

// GEMM tiling: 256 threads = 128 nodes x 2 j-halves; k-tile 32
#define GT        256
#define NODES_PB  128
#define KT        32
#define XSTR      129                    // %32==1 -> conflict-free STS & LDS
#define WTILE_FL  (KT * F_OUT)           // 1280 floats (5 KB)
#define XS_FL     (KT * XSTR)            // 4128 floats (16.5 KB)

// Scratch in __device__ globals (no allocation allowed in kernel_launch).
__device__ int    g_is64;
__device__ float  g_deg [N_MAX];
__device__ float  g_dinv[N_MAX];
__device__ int    g_rowi[E_MAX];
__device__ int    g_coli[E_MAX];
__device__ int    g_cnt [N_MAX];
__device__ int    g_cur [N_MAX];
__device__ int    g_scan[N_MAX];
__device__ int    g_ptr [N_MAX + 1];
__device__ int    g_bsum[SCAN_NB];
__device__ int    g_boff[SCAN_NB];
__device__ float  g_Wt  [F_IN * F_OUT]; // W transposed: g_Wt[k*40+j]
__device__ int2   g_rec [E_MAX];        // sorted-by-dst: {src_row, bits(norm)}
__device__ float4 g_bufA[(size_t)N_MAX * F4];
__device__ float4 g_bufB[(size_t)N_MAX * F4];

// ---- packed f32x2 helpers (FFMA2 is PTX-only on sm_103a) ----------------
__device__ __forceinline__ unsigned long long pack2(float a, float b) {
    unsigned long long r;
    asm("mov.b64 %0, {%1, %2};" : "=l"(r) : "f"(a), "f"(b));
    return r;
}
__device__ __forceinline__ void fma2(unsigned long long& d,
                                     unsigned long long a, unsigned long long b) {
    asm("fma.rn.f32x2 %0, %1, %2, %0;" : "+l"(d) : "l"(a), "l"(b));
}
__device__ __forceinline__ void unpack2(unsigned long long v, float& lo, float& hi) {
    asm("mov.b64 {%0, %1}, %2;" : "=f"(lo), "=f"(hi) : "l"(v));
}

// ---------------------------------------------------------------------------
// 1) init (+ dtype probe in thread 0)
__global__ void k_init(const void* __restrict__ ei_raw, int N) {
    int i = blockIdx.x * blockDim.x + threadIdx.x;
    if (i < N) { g_deg[i] = 1.0f; g_cnt[i] = 0; }
    if (i == 0) {
        const long long* p = (const long long*)ei_raw;
        int ok64 = 1;
        for (int k = 0; k < 64; k++) {
            long long v = p[k];
            if (v < 0 || v >= (long long)N) { ok64 = 0; break; }
        }
        g_is64 = ok64;
    }
}

__device__ __forceinline__ int load_idx(const void* ei, size_t pos, int is64, int N) {
    int v = is64 ? (int)((const long long*)ei)[pos]
                 : ((const int*)ei)[pos];
    v = v < 0 ? 0 : (v >= N ? N - 1 : v);   // clamp: never crash
    return v;
}

// 2) decode indices once; accumulate degree + histogram
__global__ void k_prep_edges(const void* __restrict__ ei,
                             const float* __restrict__ w, int E, int N) {
    int e = blockIdx.x * blockDim.x + threadIdx.x;
    if (e < E) {
        int is64 = g_is64;
        int r = load_idx(ei, (size_t)e,     is64, N);
        int c = load_idx(ei, (size_t)E + e, is64, N);
        g_rowi[e] = r;
        g_coli[e] = c;
        atomicAdd(&g_deg[c], w[e]);
        atomicAdd(&g_cnt[c], 1);
    }
}

// 2b) transpose W -> g_Wt[k*40+j]  (10240 elems, trivial)
__global__ void k_wt(const float* __restrict__ W) {
    int idx = blockIdx.x * blockDim.x + threadIdx.x;   // k*40+j
    if (idx < F_IN * F_OUT) {
        int k = idx / F_OUT, j = idx - k * F_OUT;
        g_Wt[idx] = W[j * F_IN + k];
    }
}

// ---------------------------------------------------------------------------
// 3) GEMM: z = x @ W^T -> bufA.
//    Each thread computes ONE node's HALF of the outputs (20 of 40):
//    only 10 FFMA2 accumulators (20 regs) -> high occupancy.
//    Per k-tile: W tile (5KB, contiguous from g_Wt) + x tile (transposed,
//    stride-129 conflict-free) staged in SMEM. W LDS.128 are warp-broadcast.
__global__ __launch_bounds__(GT)
void k_gemm(const float* __restrict__ x, int N) {
    __shared__ float wt[WTILE_FL];
    __shared__ float xs[XS_FL];

    int tid   = threadIdx.x;
    int node  = tid & (NODES_PB - 1);    // 0..127
    int jh    = tid >> 7;                // 0 or 1 (j-half)
    int nbase = blockIdx.x * NODES_PB;
    int gnode = nbase + node;

    unsigned long long acc[10];
#pragma unroll
    for (int j = 0; j < 10; j++) acc[j] = 0ULL;

    for (int kt = 0; kt < F_IN / KT; kt++) {
        __syncthreads();
        // stage W tile: 1280 contiguous floats = 320 float4
        for (int i = tid; i < WTILE_FL / 4; i += GT)
            ((float4*)wt)[i] = ((const float4*)(g_Wt + kt * WTILE_FL))[i];
        // stage x tile transposed: 128 nodes x 32 k; warp reads 4 full lines
#pragma unroll
        for (int i = 0; i < 4; i++) {
            int idx = tid + GT * i;          // [0,1024)
            int nd  = idx >> 3;
            int ks  = idx & 7;
            int gn  = nbase + nd;
            gn = gn < N ? gn : N - 1;
            float4 v = *(const float4*)(x + (size_t)gn * F_IN + kt * KT + ks * 4);
            int kk = ks * 4;
            xs[(kk + 0) * XSTR + nd] = v.x;
            xs[(kk + 1) * XSTR + nd] = v.y;
            xs[(kk + 2) * XSTR + nd] = v.z;
            xs[(kk + 3) * XSTR + nd] = v.w;
        }
        __syncthreads();

#pragma unroll 8
        for (int kk = 0; kk < KT; kk++) {
            float xv = xs[kk * XSTR + node];
            unsigned long long xx = pack2(xv, xv);
            // this thread's 20 W columns: 5 x ulonglong2 (16B, broadcast)
            const ulonglong2* wr =
                (const ulonglong2*)&wt[kk * F_OUT + jh * (F_OUT / 2)];
#pragma unroll
            for (int j2 = 0; j2 < 5; j2++) {
                ulonglong2 wp = wr[j2];
                fma2(acc[2 * j2 + 0], xx, wp.x);
                fma2(acc[2 * j2 + 1], xx, wp.y);
            }
        }
    }

    if (gnode < N) {
        float4* zr = g_bufA + (size_t)gnode * F4 + jh * 5;
#pragma unroll
        for (int c = 0; c < 5; c++) {
            float4 o;
            unpack2(acc[2 * c + 0], o.x, o.y);
            unpack2(acc[2 * c + 1], o.z, o.w);
            zr[c] = o;
        }
    }
}

// ---------------------------------------------------------------------------
// 4a) per-block inclusive scan of cnt
__global__ void k_scanA(int N) {
    __shared__ int s[SCAN_BS];
    int i = blockIdx.x * SCAN_BS + threadIdx.x;
    int v = (i < N) ? g_cnt[i] : 0;
    s[threadIdx.x] = v;
    __syncthreads();
#pragma unroll
    for (int off = 1; off < SCAN_BS; off <<= 1) {
        int t = (threadIdx.x >= off) ? s[threadIdx.x - off] : 0;
        __syncthreads();
        s[threadIdx.x] += t;
        __syncthreads();
    }
    if (i < N) g_scan[i] = s[threadIdx.x];
    if (threadIdx.x == SCAN_BS - 1) g_bsum[blockIdx.x] = s[threadIdx.x];
}

// 4b) serial scan of block sums (98 values)
__global__ void k_scanB(int nb) {
    if (threadIdx.x == 0 && blockIdx.x == 0) {
        int run = 0;
        for (int b = 0; b < nb; b++) { g_boff[b] = run; run += g_bsum[b]; }
    }
}

// 4c) finalize exclusive ptr; zero cursors; dinv
__global__ void k_scanC(int N) {
    int i = blockIdx.x * blockDim.x + threadIdx.x;
    if (i < N) {
        g_ptr[i + 1] = g_scan[i] + g_boff[i / SCAN_BS];
        g_cur[i] = 0;
        g_dinv[i] = rsqrtf(g_deg[i]);
        if (i == 0) g_ptr[0] = 0;
    }
}

// 5) bucket fill: sorted-by-destination edge records {src, norm}
__global__ void k_fill(const float* __restrict__ w, int E) {
    int e = blockIdx.x * blockDim.x + threadIdx.x;
    if (e < E) {
        int r = g_rowi[e];
        int c = g_coli[e];
        float nrm = g_dinv[r] * w[e] * g_dinv[c];
        int pos = g_ptr[c] + atomicAdd(&g_cur[c], 1);
        g_rec[pos] = make_int2(r, __float_as_int(nrm));
    }
}

// ---------------------------------------------------------------------------
// 6) pull hop: dst[i,:] = dinv[i]^2*src[i,:] + sum_{e: col=i} norm_e*src[row_e,:]
//    5 threads per node, 2 float4 chunks each.
template <bool AtoB>
__global__ void k_hop(int N) {
    int t = blockIdx.x * blockDim.x + threadIdx.x;
    if (t >= N * 5) return;
    const float4* __restrict__ src = AtoB ? g_bufA : g_bufB;
    float4*       __restrict__ dst = AtoB ? g_bufB : g_bufA;

    int node = t / 5;
    int q    = t - node * 5;
    int ch   = 2 * q;

    float d  = g_dinv[node];
    float d2 = d * d;
    float4 s0 = src[(size_t)node * F4 + ch];
    float4 s1 = src[(size_t)node * F4 + ch + 1];
    float4 a0 = make_float4(d2 * s0.x, d2 * s0.y, d2 * s0.z, d2 * s0.w);
    float4 a1 = make_float4(d2 * s1.x, d2 * s1.y, d2 * s1.z, d2 * s1.w);

    int beg = g_ptr[node];
    int end = g_ptr[node + 1];
    for (int e = beg; e < end; e++) {
        int2  rec = g_rec[e];
        float nrm = __int_as_float(rec.y);
        const float4* vr = &src[(size_t)rec.x * F4 + ch];
        float4 v0 = vr[0];
        float4 v1 = vr[1];
        a0.x = fmaf(nrm, v0.x, a0.x);  a0.y = fmaf(nrm, v0.y, a0.y);
        a0.z = fmaf(nrm, v0.z, a0.z);  a0.w = fmaf(nrm, v0.w, a0.w);
        a1.x = fmaf(nrm, v1.x, a1.x);  a1.y = fmaf(nrm, v1.y, a1.y);
        a1.z = fmaf(nrm, v1.z, a1.z);  a1.w = fmaf(nrm, v1.w, a1.w);
    }
    dst[(size_t)node * F4 + ch]     = a0;
    dst[(size_t)node * F4 + ch + 1] = a1;
}

// ---------------------------------------------------------------------------
// 7) epilogue: out = log_softmax(relu(h + b))
__global__ void k_final(const float* __restrict__ b,
                        float* __restrict__ out, int N) {
    int n = blockIdx.x * blockDim.x + threadIdx.x;
    if (n >= N) return;

    float v[F_OUT];
    const float4* h = g_bufA + (size_t)n * F4;
#pragma unroll
    for (int c = 0; c < F4; c++) {
        float4 t = h[c];
        v[4*c+0] = t.x; v[4*c+1] = t.y; v[4*c+2] = t.z; v[4*c+3] = t.w;
    }
#pragma unroll
    for (int j = 0; j < F_OUT; j++)
        v[j] = fmaxf(v[j] + __ldg(&b[j]), 0.0f);

    float m = -1e30f;
#pragma unroll
    for (int j = 0; j < F_OUT; j++) m = fmaxf(m, v[j]);
    float s = 0.0f;
#pragma unroll
    for (int j = 0; j < F_OUT; j++) s += expf(v[j] - m);
    float lse = m + logf(s);

    float4* o = (float4*)out + (size_t)n * F4;
#pragma unroll
    for (int c = 0; c < F4; c++)
        o[c] = make_float4(v[4*c+0] - lse, v[4*c+1] - lse,
                           v[4*c+2] - lse, v[4*c+3] - lse);
}

// ---------------------------------------------------------------------------
extern "C" void kernel_launch(void* const* d_in, const int* in_sizes, int n_in,
                              void* d_out, int out_size) {
    const float* x   = (const float*)d_in[0];
    const void*  ei  = d_in[1];
    const float* w   = (const float*)d_in[2];
    const float* W   = (const float*)d_in[3];
    const float* b   = (const float*)d_in[4];
    float*       out = (float*)d_out;

    int N = in_sizes[0] / F_IN;   // 100000
    int E = in_sizes[2];          // 1600000

    const int T = 256;
    int gN  = (N + T - 1) / T;
    int gE  = (E + T - 1) / T;
    int gH  = (N * 5 + T - 1) / T;
    int gG  = (N + NODES_PB - 1) / NODES_PB;   // 782
    int gW  = (F_IN * F_OUT + T - 1) / T;      // 40
    int nb  = (N + SCAN_BS - 1) / SCAN_BS;

    // ncu's fixed capture slot profiles my launch #3 -> GEMM goes there.
    k_init      <<<gN, T>>>(ei, N);          // 0
    k_prep_edges<<<gE, T>>>(ei, w, E, N);    // 1
    k_wt        <<<gW, T>>>(W);              // 2
    k_gemm      <<<gG, GT>>>(x, N);          // 3  <- profiled
    k_scanA     <<<nb, SCAN_BS>>>(N);        // 4
    k_scanB     <<<1, 32>>>(nb);             // 5
    k_scanC     <<<gN, T>>>(N);              // 6
    k_fill      <<<gE, T>>>(w, E);           // 7

    k_hop<true> <<<gH, T>>>(N);              // 8
    k_hop<false><<<gH, T>>>(N);              // 9

    k_final<<<gN, T>>>(b, out, N);           // 10
}

// round 9
// speedup vs baseline: 1.0904x; 1.0904x over previous
#include <cuda_runtime.h>
#include <math.h>

// Problem constants: N=100000, E=1600000, F_IN=256, F_OUT=40
#define N_MAX 100000
#define E_MAX 1600000
#define F_IN  256
#define F_OUT 40
#define F4    (F_OUT / 4)   // 10 float4 chunks per node row
#define SCAN_BS 1024
#define SCAN_NB ((N_MAX + SCAN_BS - 1) / SCAN_BS)   // 98

// GEMM tiling: 256 threads = 128 node-slots x 2 j-halves, 2 nodes/thread
#define GT        256
#define NODES_PB  256
#define KT        32
#define XSTR      257                    // %32==1 -> conflict-free STS & LDS
#define WTILE_FL  (KT * F_OUT)           // 1280 floats (5 KB)
#define XS_FL     (KT * XSTR)            // 8224 floats (32.9 KB)

// Scratch in __device__ globals (no allocation allowed in kernel_launch).
__device__ int    g_is64;
__device__ float  g_deg [N_MAX];
__device__ float  g_dinv[N_MAX];
__device__ int    g_rowi[E_MAX];
__device__ int    g_coli[E_MAX];
__device__ int    g_cnt [N_MAX];
__device__ int    g_cur [N_MAX];
__device__ int    g_scan[N_MAX];
__device__ int    g_ptr [N_MAX + 1];
__device__ int    g_bsum[SCAN_NB];
__device__ int    g_boff[SCAN_NB];
__device__ float  g_Wt  [F_IN * F_OUT]; // W transposed: g_Wt[k*40+j]
__device__ int2   g_rec [E_MAX];        // sorted-by-dst: {src_row, bits(norm)}
__device__ float4 g_bufA[(size_t)N_MAX * F4];
__device__ float4 g_bufB[(size_t)N_MAX * F4];

// ---- packed f32x2 helpers (FFMA2 is PTX-only on sm_103a) ----------------
__device__ __forceinline__ unsigned long long pack2(float a, float b) {
    unsigned long long r;
    asm("mov.b64 %0, {%1, %2};" : "=l"(r) : "f"(a), "f"(b));
    return r;
}
__device__ __forceinline__ void fma2(unsigned long long& d,
                                     unsigned long long a, unsigned long long b) {
    asm("fma.rn.f32x2 %0, %1, %2, %0;" : "+l"(d) : "l"(a), "l"(b));
}
__device__ __forceinline__ void unpack2(unsigned long long v, float& lo, float& hi) {
    asm("mov.b64 {%0, %1}, %2;" : "=f"(lo), "=f"(hi) : "l"(v));
}

// ---------------------------------------------------------------------------
// 1) init (+ dtype probe in thread 0)
__global__ void k_init(const void* __restrict__ ei_raw, int N) {
    int i = blockIdx.x * blockDim.x + threadIdx.x;
    if (i < N) { g_deg[i] = 1.0f; g_cnt[i] = 0; }
    if (i == 0) {
        const long long* p = (const long long*)ei_raw;
        int ok64 = 1;
        for (int k = 0; k < 64; k++) {
            long long v = p[k];
            if (v < 0 || v >= (long long)N) { ok64 = 0; break; }
        }
        g_is64 = ok64;
    }
}

__device__ __forceinline__ int load_idx(const void* ei, size_t pos, int is64, int N) {
    int v = is64 ? (int)((const long long*)ei)[pos]
                 : ((const int*)ei)[pos];
    v = v < 0 ? 0 : (v >= N ? N - 1 : v);   // clamp: never crash
    return v;
}

// 2) decode indices once; accumulate degree + histogram
__global__ void k_prep_edges(const void* __restrict__ ei,
                             const float* __restrict__ w, int E, int N) {
    int e = blockIdx.x * blockDim.x + threadIdx.x;
    if (e < E) {
        int is64 = g_is64;
        int r = load_idx(ei, (size_t)e,     is64, N);
        int c = load_idx(ei, (size_t)E + e, is64, N);
        g_rowi[e] = r;
        g_coli[e] = c;
        atomicAdd(&g_deg[c], w[e]);
        atomicAdd(&g_cnt[c], 1);
    }
}

// 2b) transpose W -> g_Wt[k*40+j]  (10240 elems, trivial)
__global__ void k_wt(const float* __restrict__ W) {
    int idx = blockIdx.x * blockDim.x + threadIdx.x;   // k*40+j
    if (idx < F_IN * F_OUT) {
        int k = idx / F_OUT, j = idx - k * F_OUT;
        g_Wt[idx] = W[j * F_IN + k];
    }
}

// ---------------------------------------------------------------------------
// 3) GEMM: z = x @ W^T -> bufA.
//    2x j-half register blocking: each thread computes 2 nodes x 20 outputs
//    (20 f32x2 accums = 40 regs). Each broadcast W LDS.128 now feeds 4 FFMA2
//    (20 FFMA2 per 5 W-LDS + 2 xs-LDS per kk) -> wavefronts/FFMA2 halved.
__global__ __launch_bounds__(GT)
void k_gemm(const float* __restrict__ x, int N) {
    __shared__ float wt[WTILE_FL];
    __shared__ float xs[XS_FL];

    int tid   = threadIdx.x;
    int ns    = tid & 127;               // node slot 0..127
    int jh    = tid >> 7;                // j-half 0/1
    int nbase = blockIdx.x * NODES_PB;
    int node0 = nbase + ns;
    int node1 = node0 + 128;

    unsigned long long acc0[10], acc1[10];
#pragma unroll
    for (int j = 0; j < 10; j++) { acc0[j] = 0ULL; acc1[j] = 0ULL; }

    for (int kt = 0; kt < F_IN / KT; kt++) {
        __syncthreads();
        // stage W tile: 1280 contiguous floats = 320 float4
        for (int i = tid; i < WTILE_FL / 4; i += GT)
            ((float4*)wt)[i] = ((const float4*)(g_Wt + kt * WTILE_FL))[i];
        // stage x tile transposed: 256 nodes x 32 k = 2048 float4, 8/thread.
        // warp: 4 nodes x 8 ksegs -> 4 full 128B lines; STS conflict-free.
#pragma unroll
        for (int i = 0; i < 8; i++) {
            int idx = tid + GT * i;          // [0,2048)
            int nd  = idx >> 3;
            int ks  = idx & 7;
            int gn  = nbase + nd;
            gn = gn < N ? gn : N - 1;
            float4 v = *(const float4*)(x + (size_t)gn * F_IN + kt * KT + ks * 4);
            int kk = ks * 4;
            xs[(kk + 0) * XSTR + nd] = v.x;
            xs[(kk + 1) * XSTR + nd] = v.y;
            xs[(kk + 2) * XSTR + nd] = v.z;
            xs[(kk + 3) * XSTR + nd] = v.w;
        }
        __syncthreads();

#pragma unroll 16
        for (int kk = 0; kk < KT; kk++) {
            float x0 = xs[kk * XSTR + ns];
            float x1 = xs[kk * XSTR + ns + 128];
            unsigned long long xx0 = pack2(x0, x0);
            unsigned long long xx1 = pack2(x1, x1);
            const ulonglong2* wr =
                (const ulonglong2*)&wt[kk * F_OUT + jh * (F_OUT / 2)];
#pragma unroll
            for (int j2 = 0; j2 < 5; j2++) {
                ulonglong2 wp = wr[j2];
                fma2(acc0[2 * j2 + 0], xx0, wp.x);
                fma2(acc0[2 * j2 + 1], xx0, wp.y);
                fma2(acc1[2 * j2 + 0], xx1, wp.x);
                fma2(acc1[2 * j2 + 1], xx1, wp.y);
            }
        }
    }

    if (node0 < N) {
        float4* zr = g_bufA + (size_t)node0 * F4 + jh * 5;
#pragma unroll
        for (int c = 0; c < 5; c++) {
            float4 o;
            unpack2(acc0[2 * c + 0], o.x, o.y);
            unpack2(acc0[2 * c + 1], o.z, o.w);
            zr[c] = o;
        }
    }
    if (node1 < N) {
        float4* zr = g_bufA + (size_t)node1 * F4 + jh * 5;
#pragma unroll
        for (int c = 0; c < 5; c++) {
            float4 o;
            unpack2(acc1[2 * c + 0], o.x, o.y);
            unpack2(acc1[2 * c + 1], o.z, o.w);
            zr[c] = o;
        }
    }
}

// ---------------------------------------------------------------------------
// 4a) per-block inclusive scan of cnt
__global__ void k_scanA(int N) {
    __shared__ int s[SCAN_BS];
    int i = blockIdx.x * SCAN_BS + threadIdx.x;
    int v = (i < N) ? g_cnt[i] : 0;
    s[threadIdx.x] = v;
    __syncthreads();
#pragma unroll
    for (int off = 1; off < SCAN_BS; off <<= 1) {
        int t = (threadIdx.x >= off) ? s[threadIdx.x - off] : 0;
        __syncthreads();
        s[threadIdx.x] += t;
        __syncthreads();
    }
    if (i < N) g_scan[i] = s[threadIdx.x];
    if (threadIdx.x == SCAN_BS - 1) g_bsum[blockIdx.x] = s[threadIdx.x];
}

// 4b) serial scan of block sums (98 values)
__global__ void k_scanB(int nb) {
    if (threadIdx.x == 0 && blockIdx.x == 0) {
        int run = 0;
        for (int b = 0; b < nb; b++) { g_boff[b] = run; run += g_bsum[b]; }
    }
}

// 4c) finalize exclusive ptr; zero cursors; dinv
__global__ void k_scanC(int N) {
    int i = blockIdx.x * blockDim.x + threadIdx.x;
    if (i < N) {
        g_ptr[i + 1] = g_scan[i] + g_boff[i / SCAN_BS];
        g_cur[i] = 0;
        g_dinv[i] = rsqrtf(g_deg[i]);
        if (i == 0) g_ptr[0] = 0;
    }
}

// 5) bucket fill: sorted-by-destination edge records {src, norm}
__global__ void k_fill(const float* __restrict__ w, int E) {
    int e = blockIdx.x * blockDim.x + threadIdx.x;
    if (e < E) {
        int r = g_rowi[e];
        int c = g_coli[e];
        float nrm = g_dinv[r] * w[e] * g_dinv[c];
        int pos = g_ptr[c] + atomicAdd(&g_cur[c], 1);
        g_rec[pos] = make_int2(r, __float_as_int(nrm));
    }
}

// ---------------------------------------------------------------------------
// 6) pull hop: dst[i,:] = dinv[i]^2*src[i,:] + sum_{e: col=i} norm_e*src[row_e,:]
//    5 threads per node, 2 float4 chunks each.
template <bool AtoB>
__global__ void k_hop(int N) {
    int t = blockIdx.x * blockDim.x + threadIdx.x;
    if (t >= N * 5) return;
    const float4* __restrict__ src = AtoB ? g_bufA : g_bufB;
    float4*       __restrict__ dst = AtoB ? g_bufB : g_bufA;

    int node = t / 5;
    int q    = t - node * 5;
    int ch   = 2 * q;

    float d  = g_dinv[node];
    float d2 = d * d;
    float4 s0 = src[(size_t)node * F4 + ch];
    float4 s1 = src[(size_t)node * F4 + ch + 1];
    float4 a0 = make_float4(d2 * s0.x, d2 * s0.y, d2 * s0.z, d2 * s0.w);
    float4 a1 = make_float4(d2 * s1.x, d2 * s1.y, d2 * s1.z, d2 * s1.w);

    int beg = g_ptr[node];
    int end = g_ptr[node + 1];
    for (int e = beg; e < end; e++) {
        int2  rec = g_rec[e];
        float nrm = __int_as_float(rec.y);
        const float4* vr = &src[(size_t)rec.x * F4 + ch];
        float4 v0 = vr[0];
        float4 v1 = vr[1];
        a0.x = fmaf(nrm, v0.x, a0.x);  a0.y = fmaf(nrm, v0.y, a0.y);
        a0.z = fmaf(nrm, v0.z, a0.z);  a0.w = fmaf(nrm, v0.w, a0.w);
        a1.x = fmaf(nrm, v1.x, a1.x);  a1.y = fmaf(nrm, v1.y, a1.y);
        a1.z = fmaf(nrm, v1.z, a1.z);  a1.w = fmaf(nrm, v1.w, a1.w);
    }
    dst[(size_t)node * F4 + ch]     = a0;
    dst[(size_t)node * F4 + ch + 1] = a1;
}

// ---------------------------------------------------------------------------
// 7) epilogue: out = log_softmax(relu(h + b))
__global__ void k_final(const float* __restrict__ b,
                        float* __restrict__ out, int N) {
    int n = blockIdx.x * blockDim.x + threadIdx.x;
    if (n >= N) return;

    float v[F_OUT];
    const float4* h = g_bufA + (size_t)n * F4;
#pragma unroll
    for (int c = 0; c < F4; c++) {
        float4 t = h[c];
        v[4*c+0] = t.x; v[4*c+1] = t.y; v[4*c+2] = t.z; v[4*c+3] = t.w;
    }
#pragma unroll
    for (int j = 0; j < F_OUT; j++)
        v[j] = fmaxf(v[j] + __ldg(&b[j]), 0.0f);

    float m = -1e30f;
#pragma unroll
    for (int j = 0; j < F_OUT; j++) m = fmaxf(m, v[j]);
    float s = 0.0f;
#pragma unroll
    for (int j = 0; j < F_OUT; j++) s += expf(v[j] - m);
    float lse = m + logf(s);

    float4* o = (float4*)out + (size_t)n * F4;
#pragma unroll
    for (int c = 0; c < F4; c++)
        o[c] = make_float4(v[4*c+0] - lse, v[4*c+1] - lse,
                           v[4*c+2] - lse, v[4*c+3] - lse);
}

// ---------------------------------------------------------------------------
extern "C" void kernel_launch(void* const* d_in, const int* in_sizes, int n_in,
                              void* d_out, int out_size) {
    const float* x   = (const float*)d_in[0];
    const void*  ei  = d_in[1];
    const float* w   = (const float*)d_in[2];
    const float* W   = (const float*)d_in[3];
    const float* b   = (const float*)d_in[4];
    float*       out = (float*)d_out;

    int N = in_sizes[0] / F_IN;   // 100000
    int E = in_sizes[2];          // 1600000

    const int T = 256;
    int gN  = (N + T - 1) / T;
    int gE  = (E + T - 1) / T;
    int gH  = (N * 5 + T - 1) / T;
    int gG  = (N + NODES_PB - 1) / NODES_PB;   // 391
    int gW  = (F_IN * F_OUT + T - 1) / T;      // 40
    int nb  = (N + SCAN_BS - 1) / SCAN_BS;

    // ncu's fixed capture slot profiles my launch #3 -> GEMM goes there.
    k_init      <<<gN, T>>>(ei, N);          // 0
    k_prep_edges<<<gE, T>>>(ei, w, E, N);    // 1
    k_wt        <<<gW, T>>>(W);              // 2
    k_gemm      <<<gG, GT>>>(x, N);          // 3  <- profiled
    k_scanA     <<<nb, SCAN_BS>>>(N);        // 4
    k_scanB     <<<1, 32>>>(nb);             // 5
    k_scanC     <<<gN, T>>>(N);              // 6
    k_fill      <<<gE, T>>>(w, E);           // 7

    k_hop<true> <<<gH, T>>>(N);              // 8
    k_hop<false><<<gH, T>>>(N);              // 9

    k_final<<<gN, T>>>(b, out, N);           // 10
}

// round 10
// speedup vs baseline: 1.1317x; 1.0379x over previous
#include <cuda_runtime.h>
#include <math.h>

// Problem constants: N=100000, E=1600000, F_IN=256, F_OUT=40
#define N_MAX 100000
#define E_MAX 1600000
#define F_IN  256
#define F_OUT 40
#define F4    (F_OUT / 4)   // 10 float4 chunks per node row
#define SCAN_BS 1024
#define SCAN_NB ((N_MAX + SCAN_BS - 1) / SCAN_BS)   // 98

// GEMM tiling: 256 threads = 128 node-slots x 2 j-halves, 2 nodes/thread
#define GT        256
#define NODES_PB  256
#define KT        32
#define XSTR      257                    // %32==1 -> conflict-free STS & LDS
#define WTILE_FL  (KT * F_OUT)           // 1280 floats (5 KB)
#define XS_FL     (KT * XSTR)            // 8224 floats (32.9 KB)

// Scratch in __device__ globals (no allocation allowed in kernel_launch).
__device__ int    g_is64;
__device__ float  g_deg [N_MAX];
__device__ float  g_dinv[N_MAX];
__device__ int    g_rowi[E_MAX];
__device__ int    g_coli[E_MAX];
__device__ int    g_cnt [N_MAX];
__device__ int    g_cur [N_MAX];
__device__ int    g_scan[N_MAX];
__device__ int    g_ptr [N_MAX + 1];
__device__ int    g_bsum[SCAN_NB];
__device__ int    g_boff[SCAN_NB];
__device__ float  g_Wt  [F_IN * F_OUT]; // W transposed: g_Wt[k*40+j]
__device__ int2   g_rec [E_MAX];        // sorted-by-dst: {src_row, bits(norm)}
__device__ float4 g_bufA[(size_t)N_MAX * F4];
__device__ float4 g_bufB[(size_t)N_MAX * F4];

// ---- packed f32x2 helpers (FFMA2 is PTX-only on sm_103a) ----------------
__device__ __forceinline__ unsigned long long pack2(float a, float b) {
    unsigned long long r;
    asm("mov.b64 %0, {%1, %2};" : "=l"(r) : "f"(a), "f"(b));
    return r;
}
__device__ __forceinline__ void fma2(unsigned long long& d,
                                     unsigned long long a, unsigned long long b) {
    asm("fma.rn.f32x2 %0, %1, %2, %0;" : "+l"(d) : "l"(a), "l"(b));
}
__device__ __forceinline__ void unpack2(unsigned long long v, float& lo, float& hi) {
    asm("mov.b64 {%0, %1}, %2;" : "=f"(lo), "=f"(hi) : "l"(v));
}

// ---------------------------------------------------------------------------
// 1) init (+ dtype probe in thread 0)
__global__ void k_init(const void* __restrict__ ei_raw, int N) {
    int i = blockIdx.x * blockDim.x + threadIdx.x;
    if (i < N) { g_deg[i] = 1.0f; g_cnt[i] = 0; }
    if (i == 0) {
        const long long* p = (const long long*)ei_raw;
        int ok64 = 1;
        for (int k = 0; k < 64; k++) {
            long long v = p[k];
            if (v < 0 || v >= (long long)N) { ok64 = 0; break; }
        }
        g_is64 = ok64;
    }
}

__device__ __forceinline__ int load_idx(const void* ei, size_t pos, int is64, int N) {
    int v = is64 ? (int)((const long long*)ei)[pos]
                 : ((const int*)ei)[pos];
    v = v < 0 ? 0 : (v >= N ? N - 1 : v);   // clamp: never crash
    return v;
}

// 2) decode indices once; accumulate degree + histogram
__global__ void k_prep_edges(const void* __restrict__ ei,
                             const float* __restrict__ w, int E, int N) {
    int e = blockIdx.x * blockDim.x + threadIdx.x;
    if (e < E) {
        int is64 = g_is64;
        int r = load_idx(ei, (size_t)e,     is64, N);
        int c = load_idx(ei, (size_t)E + e, is64, N);
        g_rowi[e] = r;
        g_coli[e] = c;
        atomicAdd(&g_deg[c], w[e]);
        atomicAdd(&g_cnt[c], 1);
    }
}

// 2b) transpose W -> g_Wt[k*40+j]  (10240 elems, trivial)
__global__ void k_wt(const float* __restrict__ W) {
    int idx = blockIdx.x * blockDim.x + threadIdx.x;   // k*40+j
    if (idx < F_IN * F_OUT) {
        int k = idx / F_OUT, j = idx - k * F_OUT;
        g_Wt[idx] = W[j * F_IN + k];
    }
}

// ---------------------------------------------------------------------------
// 3) GEMM: z = x @ W^T -> bufA.
//    2x j-half register blocking (20 f32x2 accums = 40 regs).
//    __launch_bounds__(256,3): 3 blocks/SM -> 24 warps AND single wave
//    (391 blocks / 444 resident), killing the R9 1.32-wave tail.
//    Staging loop unroll-limited to 4 to keep live regs under the 85 cap.
__global__ __launch_bounds__(GT, 3)
void k_gemm(const float* __restrict__ x, int N) {
    __shared__ float wt[WTILE_FL];
    __shared__ float xs[XS_FL];

    int tid   = threadIdx.x;
    int ns    = tid & 127;               // node slot 0..127
    int jh    = tid >> 7;                // j-half 0/1
    int nbase = blockIdx.x * NODES_PB;
    int node0 = nbase + ns;
    int node1 = node0 + 128;

    unsigned long long acc0[10], acc1[10];
#pragma unroll
    for (int j = 0; j < 10; j++) { acc0[j] = 0ULL; acc1[j] = 0ULL; }

    for (int kt = 0; kt < F_IN / KT; kt++) {
        __syncthreads();
        // stage W tile: 1280 contiguous floats = 320 float4
        for (int i = tid; i < WTILE_FL / 4; i += GT)
            ((float4*)wt)[i] = ((const float4*)(g_Wt + kt * WTILE_FL))[i];
        // stage x tile transposed: 256 nodes x 32 k = 2048 float4, 8/thread.
        // unroll 4 bounds in-flight loads (register budget for occ=3).
#pragma unroll 4
        for (int i = 0; i < 8; i++) {
            int idx = tid + GT * i;          // [0,2048)
            int nd  = idx >> 3;
            int ks  = idx & 7;
            int gn  = nbase + nd;
            gn = gn < N ? gn : N - 1;
            float4 v = *(const float4*)(x + (size_t)gn * F_IN + kt * KT + ks * 4);
            int kk = ks * 4;
            xs[(kk + 0) * XSTR + nd] = v.x;
            xs[(kk + 1) * XSTR + nd] = v.y;
            xs[(kk + 2) * XSTR + nd] = v.z;
            xs[(kk + 3) * XSTR + nd] = v.w;
        }
        __syncthreads();

#pragma unroll 16
        for (int kk = 0; kk < KT; kk++) {
            float x0 = xs[kk * XSTR + ns];
            float x1 = xs[kk * XSTR + ns + 128];
            unsigned long long xx0 = pack2(x0, x0);
            unsigned long long xx1 = pack2(x1, x1);
            const ulonglong2* wr =
                (const ulonglong2*)&wt[kk * F_OUT + jh * (F_OUT / 2)];
#pragma unroll
            for (int j2 = 0; j2 < 5; j2++) {
                ulonglong2 wp = wr[j2];
                fma2(acc0[2 * j2 + 0], xx0, wp.x);
                fma2(acc0[2 * j2 + 1], xx0, wp.y);
                fma2(acc1[2 * j2 + 0], xx1, wp.x);
                fma2(acc1[2 * j2 + 1], xx1, wp.y);
            }
        }
    }

    if (node0 < N) {
        float4* zr = g_bufA + (size_t)node0 * F4 + jh * 5;
#pragma unroll
        for (int c = 0; c < 5; c++) {
            float4 o;
            unpack2(acc0[2 * c + 0], o.x, o.y);
            unpack2(acc0[2 * c + 1], o.z, o.w);
            zr[c] = o;
        }
    }
    if (node1 < N) {
        float4* zr = g_bufA + (size_t)node1 * F4 + jh * 5;
#pragma unroll
        for (int c = 0; c < 5; c++) {
            float4 o;
            unpack2(acc1[2 * c + 0], o.x, o.y);
            unpack2(acc1[2 * c + 1], o.z, o.w);
            zr[c] = o;
        }
    }
}

// ---------------------------------------------------------------------------
// 4a) per-block inclusive scan of cnt
__global__ void k_scanA(int N) {
    __shared__ int s[SCAN_BS];
    int i = blockIdx.x * SCAN_BS + threadIdx.x;
    int v = (i < N) ? g_cnt[i] : 0;
    s[threadIdx.x] = v;
    __syncthreads();
#pragma unroll
    for (int off = 1; off < SCAN_BS; off <<= 1) {
        int t = (threadIdx.x >= off) ? s[threadIdx.x - off] : 0;
        __syncthreads();
        s[threadIdx.x] += t;
        __syncthreads();
    }
    if (i < N) g_scan[i] = s[threadIdx.x];
    if (threadIdx.x == SCAN_BS - 1) g_bsum[blockIdx.x] = s[threadIdx.x];
}

// 4b) parallel exclusive scan of block sums (nb <= 128): shfl + smem combine
__global__ void k_scanB(int nb) {
    __shared__ int warp_tot[4];
    int t = threadIdx.x;                 // 128 threads
    int v = (t < nb) ? g_bsum[t] : 0;
    int lane = t & 31, wid = t >> 5;
    int inc = v;
#pragma unroll
    for (int off = 1; off < 32; off <<= 1) {
        int u = __shfl_up_sync(0xffffffff, inc, off);
        if (lane >= off) inc += u;
    }
    if (lane == 31) warp_tot[wid] = inc;
    __syncthreads();
    int base = 0;
#pragma unroll
    for (int wj = 0; wj < 4; wj++)
        base += (wj < wid) ? warp_tot[wj] : 0;
    if (t < nb) g_boff[t] = base + inc - v;   // exclusive
}

// 4c) finalize exclusive ptr; zero cursors; dinv
__global__ void k_scanC(int N) {
    int i = blockIdx.x * blockDim.x + threadIdx.x;
    if (i < N) {
        g_ptr[i + 1] = g_scan[i] + g_boff[i / SCAN_BS];
        g_cur[i] = 0;
        g_dinv[i] = rsqrtf(g_deg[i]);
        if (i == 0) g_ptr[0] = 0;
    }
}

// 5) bucket fill: sorted-by-destination edge records {src, norm}
__global__ void k_fill(const float* __restrict__ w, int E) {
    int e = blockIdx.x * blockDim.x + threadIdx.x;
    if (e < E) {
        int r = g_rowi[e];
        int c = g_coli[e];
        float nrm = g_dinv[r] * w[e] * g_dinv[c];
        int pos = g_ptr[c] + atomicAdd(&g_cur[c], 1);
        g_rec[pos] = make_int2(r, __float_as_int(nrm));
    }
}

// ---------------------------------------------------------------------------
// 6) pull hop: dst[i,:] = dinv[i]^2*src[i,:] + sum_{e: col=i} norm_e*src[row_e,:]
//    5 threads per node, 2 float4 chunks each.
template <bool AtoB>
__global__ void k_hop(int N) {
    int t = blockIdx.x * blockDim.x + threadIdx.x;
    if (t >= N * 5) return;
    const float4* __restrict__ src = AtoB ? g_bufA : g_bufB;
    float4*       __restrict__ dst = AtoB ? g_bufB : g_bufA;

    int node = t / 5;
    int q    = t - node * 5;
    int ch   = 2 * q;

    float d  = g_dinv[node];
    float d2 = d * d;
    float4 s0 = src[(size_t)node * F4 + ch];
    float4 s1 = src[(size_t)node * F4 + ch + 1];
    float4 a0 = make_float4(d2 * s0.x, d2 * s0.y, d2 * s0.z, d2 * s0.w);
    float4 a1 = make_float4(d2 * s1.x, d2 * s1.y, d2 * s1.z, d2 * s1.w);

    int beg = g_ptr[node];
    int end = g_ptr[node + 1];
    for (int e = beg; e < end; e++) {
        int2  rec = g_rec[e];
        float nrm = __int_as_float(rec.y);
        const float4* vr = &src[(size_t)rec.x * F4 + ch];
        float4 v0 = vr[0];
        float4 v1 = vr[1];
        a0.x = fmaf(nrm, v0.x, a0.x);  a0.y = fmaf(nrm, v0.y, a0.y);
        a0.z = fmaf(nrm, v0.z, a0.z);  a0.w = fmaf(nrm, v0.w, a0.w);
        a1.x = fmaf(nrm, v1.x, a1.x);  a1.y = fmaf(nrm, v1.y, a1.y);
        a1.z = fmaf(nrm, v1.z, a1.z);  a1.w = fmaf(nrm, v1.w, a1.w);
    }
    dst[(size_t)node * F4 + ch]     = a0;
    dst[(size_t)node * F4 + ch + 1] = a1;
}

// ---------------------------------------------------------------------------
// 7) epilogue: out = log_softmax(relu(h + b))
__global__ void k_final(const float* __restrict__ b,
                        float* __restrict__ out, int N) {
    int n = blockIdx.x * blockDim.x + threadIdx.x;
    if (n >= N) return;

    float v[F_OUT];
    const float4* h = g_bufA + (size_t)n * F4;
#pragma unroll
    for (int c = 0; c < F4; c++) {
        float4 t = h[c];
        v[4*c+0] = t.x; v[4*c+1] = t.y; v[4*c+2] = t.z; v[4*c+3] = t.w;
    }
#pragma unroll
    for (int j = 0; j < F_OUT; j++)
        v[j] = fmaxf(v[j] + __ldg(&b[j]), 0.0f);

    float m = -1e30f;
#pragma unroll
    for (int j = 0; j < F_OUT; j++) m = fmaxf(m, v[j]);
    float s = 0.0f;
#pragma unroll
    for (int j = 0; j < F_OUT; j++) s += expf(v[j] - m);
    float lse = m + logf(s);

    float4* o = (float4*)out + (size_t)n * F4;
#pragma unroll
    for (int c = 0; c < F4; c++)
        o[c] = make_float4(v[4*c+0] - lse, v[4*c+1] - lse,
                           v[4*c+2] - lse, v[4*c+3] - lse);
}

// ---------------------------------------------------------------------------
extern "C" void kernel_launch(void* const* d_in, const int* in_sizes, int n_in,
                              void* d_out, int out_size) {
    const float* x   = (const float*)d_in[0];
    const void*  ei  = d_in[1];
    const float* w   = (const float*)d_in[2];
    const float* W   = (const float*)d_in[3];
    const float* b   = (const float*)d_in[4];
    float*       out = (float*)d_out;

    int N = in_sizes[0] / F_IN;   // 100000
    int E = in_sizes[2];          // 1600000

    const int T = 256;
    int gN  = (N + T - 1) / T;
    int gE  = (E + T - 1) / T;
    int gH  = (N * 5 + T - 1) / T;
    int gG  = (N + NODES_PB - 1) / NODES_PB;   // 391
    int gW  = (F_IN * F_OUT + T - 1) / T;      // 40
    int nb  = (N + SCAN_BS - 1) / SCAN_BS;

    // ncu's fixed capture slot profiles my launch #3 -> GEMM goes there.
    k_init      <<<gN, T>>>(ei, N);          // 0
    k_prep_edges<<<gE, T>>>(ei, w, E, N);    // 1
    k_wt        <<<gW, T>>>(W);              // 2
    k_gemm      <<<gG, GT>>>(x, N);          // 3  <- profiled
    k_scanA     <<<nb, SCAN_BS>>>(N);        // 4
    k_scanB     <<<1, 128>>>(nb);            // 5
    k_scanC     <<<gN, T>>>(N);              // 6
    k_fill      <<<gE, T>>>(w, E);           // 7

    k_hop<true> <<<gH, T>>>(N);              // 8
    k_hop<false><<<gH, T>>>(N);              // 9

    k_final<<<gN, T>>>(b, out, N);           // 10
}

// round 11
// speedup vs baseline: 1.1985x; 1.0590x over previous
#include <cuda_runtime.h>
#include <math.h>

// Problem constants: N=100000, E=1600000, F_IN=256, F_OUT=40
#define N_MAX 100000
#define E_MAX 1600000
#define F_IN  256
#define F_OUT 40
#define F4    (F_OUT / 4)   // 10 float4 chunks per node row
#define SCAN_BS 1024
#define SCAN_NB ((N_MAX + SCAN_BS - 1) / SCAN_BS)   // 98

// GEMM tiling: 256 threads = 128 node-slots x 2 j-halves, 2 nodes/thread
#define GT        256
#define NODES_PB  256
#define KT        32
#define XSTR      257                    // %32==1 -> conflict-free STS & LDS
#define WT_FL     (F_IN * F_OUT)         // full Wt resident: 10240 fl (40 KB)
#define XS_FL     (KT * XSTR)            // 8224 floats (32.9 KB)

// Hop tiling: 320 threads = 64 nodes x 5 chunk-pairs
#define HT        320
#define HNODES    64
#define HCAP      5120                   // staged records (40 KB int2)

// Scratch in __device__ globals (no allocation allowed in kernel_launch).
__device__ int    g_is64;
__device__ float  g_deg [N_MAX];
__device__ float  g_dinv[N_MAX];
__device__ int    g_rowi[E_MAX];
__device__ int    g_coli[E_MAX];
__device__ int    g_cnt [N_MAX];
__device__ int    g_cur [N_MAX];
__device__ int    g_scan[N_MAX];
__device__ int    g_ptr [N_MAX + 1];
__device__ int    g_bsum[SCAN_NB];
__device__ int    g_boff[SCAN_NB];
__device__ float  g_Wt  [F_IN * F_OUT]; // W transposed: g_Wt[k*40+j]
__device__ int2   g_rec [E_MAX];        // sorted-by-dst: {src_row, bits(norm)}
__device__ float4 g_bufA[(size_t)N_MAX * F4];
__device__ float4 g_bufB[(size_t)N_MAX * F4];

// ---- packed f32x2 helpers (FFMA2 is PTX-only on sm_103a) ----------------
__device__ __forceinline__ unsigned long long pack2(float a, float b) {
    unsigned long long r;
    asm("mov.b64 %0, {%1, %2};" : "=l"(r) : "f"(a), "f"(b));
    return r;
}
__device__ __forceinline__ void fma2(unsigned long long& d,
                                     unsigned long long a, unsigned long long b) {
    asm("fma.rn.f32x2 %0, %1, %2, %0;" : "+l"(d) : "l"(a), "l"(b));
}
__device__ __forceinline__ void unpack2(unsigned long long v, float& lo, float& hi) {
    asm("mov.b64 {%0, %1}, %2;" : "=f"(lo), "=f"(hi) : "l"(v));
}

// ---------------------------------------------------------------------------
// 1) init (+ dtype probe in thread 0)
__global__ void k_init(const void* __restrict__ ei_raw, int N) {
    int i = blockIdx.x * blockDim.x + threadIdx.x;
    if (i < N) { g_deg[i] = 1.0f; g_cnt[i] = 0; }
    if (i == 0) {
        const long long* p = (const long long*)ei_raw;
        int ok64 = 1;
        for (int k = 0; k < 64; k++) {
            long long v = p[k];
            if (v < 0 || v >= (long long)N) { ok64 = 0; break; }
        }
        g_is64 = ok64;
    }
}

__device__ __forceinline__ int load_idx(const void* ei, size_t pos, int is64, int N) {
    int v = is64 ? (int)((const long long*)ei)[pos]
                 : ((const int*)ei)[pos];
    v = v < 0 ? 0 : (v >= N ? N - 1 : v);   // clamp: never crash
    return v;
}

// 2) decode indices once; accumulate degree + histogram
__global__ void k_prep_edges(const void* __restrict__ ei,
                             const float* __restrict__ w, int E, int N) {
    int e = blockIdx.x * blockDim.x + threadIdx.x;
    if (e < E) {
        int is64 = g_is64;
        int r = load_idx(ei, (size_t)e,     is64, N);
        int c = load_idx(ei, (size_t)E + e, is64, N);
        g_rowi[e] = r;
        g_coli[e] = c;
        atomicAdd(&g_deg[c], w[e]);
        atomicAdd(&g_cnt[c], 1);
    }
}

// 2b) transpose W -> g_Wt[k*40+j]  (10240 elems, trivial)
__global__ void k_wt(const float* __restrict__ W) {
    int idx = blockIdx.x * blockDim.x + threadIdx.x;   // k*40+j
    if (idx < F_IN * F_OUT) {
        int k = idx / F_OUT, j = idx - k * F_OUT;
        g_Wt[idx] = W[j * F_IN + k];
    }
}

// ---------------------------------------------------------------------------
// 3) GEMM: z = x @ W^T -> bufA.  Software-pipelined:
//    - full Wt resident in SMEM (loaded once, no per-kt W staging)
//    - x tile kt+1 LDG'd into registers BEFORE computing tile kt, STS'd
//      after the compute barrier -> DRAM latency hidden behind 32-kk compute.
//    2x j-half register blocking (20 f32x2 accums).
__device__ __forceinline__ void gemm_ldtile(const float* __restrict__ x,
                                            int nbase, int kt, int N, int tid,
                                            float4 (&r)[8]) {
#pragma unroll
    for (int i = 0; i < 8; i++) {
        int idx = tid + GT * i;          // [0,2048)
        int nd  = idx >> 3;
        int ks  = idx & 7;
        int gn  = nbase + nd;
        gn = gn < N ? gn : N - 1;
        r[i] = *(const float4*)(x + (size_t)gn * F_IN + kt * KT + ks * 4);
    }
}

__global__ __launch_bounds__(GT, 2)
void k_gemm(const float* __restrict__ x, int N) {
    __shared__ float wt[WT_FL];          // 40 KB, whole Wt
    __shared__ float xs[XS_FL];          // 32.9 KB, one x tile (transposed)

    int tid   = threadIdx.x;
    int ns    = tid & 127;               // node slot 0..127
    int jh    = tid >> 7;                // j-half 0/1
    int nbase = blockIdx.x * NODES_PB;
    int node0 = nbase + ns;
    int node1 = node0 + 128;

    // preload whole Wt (2560 float4, 10 per thread)
#pragma unroll
    for (int i = 0; i < WT_FL / 4 / GT; i++)
        ((float4*)wt)[tid + GT * i] = ((const float4*)g_Wt)[tid + GT * i];

    unsigned long long acc0[10], acc1[10];
#pragma unroll
    for (int j = 0; j < 10; j++) { acc0[j] = 0ULL; acc1[j] = 0ULL; }

    float4 r[8];
    gemm_ldtile(x, nbase, 0, N, tid, r);       // prologue: tile 0 in flight

    for (int kt = 0; kt < F_IN / KT; kt++) {
        __syncthreads();                        // xs free from previous compute
        // STS prefetched tile (transposed scatter, conflict-free)
#pragma unroll
        for (int i = 0; i < 8; i++) {
            int idx = tid + GT * i;
            int nd  = idx >> 3;
            int kk  = (idx & 7) * 4;
            xs[(kk + 0) * XSTR + nd] = r[i].x;
            xs[(kk + 1) * XSTR + nd] = r[i].y;
            xs[(kk + 2) * XSTR + nd] = r[i].z;
            xs[(kk + 3) * XSTR + nd] = r[i].w;
        }
        __syncthreads();
        if (kt + 1 < F_IN / KT)                 // prefetch next tile: LDGs
            gemm_ldtile(x, nbase, kt + 1, N, tid, r);  // overlap compute below

#pragma unroll 16
        for (int kk = 0; kk < KT; kk++) {
            float x0 = xs[kk * XSTR + ns];
            float x1 = xs[kk * XSTR + ns + 128];
            unsigned long long xx0 = pack2(x0, x0);
            unsigned long long xx1 = pack2(x1, x1);
            const ulonglong2* wr =
                (const ulonglong2*)&wt[(kt * KT + kk) * F_OUT + jh * (F_OUT / 2)];
#pragma unroll
            for (int j2 = 0; j2 < 5; j2++) {
                ulonglong2 wp = wr[j2];
                fma2(acc0[2 * j2 + 0], xx0, wp.x);
                fma2(acc0[2 * j2 + 1], xx0, wp.y);
                fma2(acc1[2 * j2 + 0], xx1, wp.x);
                fma2(acc1[2 * j2 + 1], xx1, wp.y);
            }
        }
    }

    if (node0 < N) {
        float4* zr = g_bufA + (size_t)node0 * F4 + jh * 5;
#pragma unroll
        for (int c = 0; c < 5; c++) {
            float4 o;
            unpack2(acc0[2 * c + 0], o.x, o.y);
            unpack2(acc0[2 * c + 1], o.z, o.w);
            zr[c] = o;
        }
    }
    if (node1 < N) {
        float4* zr = g_bufA + (size_t)node1 * F4 + jh * 5;
#pragma unroll
        for (int c = 0; c < 5; c++) {
            float4 o;
            unpack2(acc1[2 * c + 0], o.x, o.y);
            unpack2(acc1[2 * c + 1], o.z, o.w);
            zr[c] = o;
        }
    }
}

// ---------------------------------------------------------------------------
// 4a) per-block inclusive scan of cnt
__global__ void k_scanA(int N) {
    __shared__ int s[SCAN_BS];
    int i = blockIdx.x * SCAN_BS + threadIdx.x;
    int v = (i < N) ? g_cnt[i] : 0;
    s[threadIdx.x] = v;
    __syncthreads();
#pragma unroll
    for (int off = 1; off < SCAN_BS; off <<= 1) {
        int t = (threadIdx.x >= off) ? s[threadIdx.x - off] : 0;
        __syncthreads();
        s[threadIdx.x] += t;
        __syncthreads();
    }
    if (i < N) g_scan[i] = s[threadIdx.x];
    if (threadIdx.x == SCAN_BS - 1) g_bsum[blockIdx.x] = s[threadIdx.x];
}

// 4b) parallel exclusive scan of block sums (nb <= 128): shfl + smem combine
__global__ void k_scanB(int nb) {
    __shared__ int warp_tot[4];
    int t = threadIdx.x;                 // 128 threads
    int v = (t < nb) ? g_bsum[t] : 0;
    int lane = t & 31, wid = t >> 5;
    int inc = v;
#pragma unroll
    for (int off = 1; off < 32; off <<= 1) {
        int u = __shfl_up_sync(0xffffffff, inc, off);
        if (lane >= off) inc += u;
    }
    if (lane == 31) warp_tot[wid] = inc;
    __syncthreads();
    int base = 0;
#pragma unroll
    for (int wj = 0; wj < 4; wj++)
        base += (wj < wid) ? warp_tot[wj] : 0;
    if (t < nb) g_boff[t] = base + inc - v;   // exclusive
}

// 4c) finalize exclusive ptr; zero cursors; dinv
__global__ void k_scanC(int N) {
    int i = blockIdx.x * blockDim.x + threadIdx.x;
    if (i < N) {
        g_ptr[i + 1] = g_scan[i] + g_boff[i / SCAN_BS];
        g_cur[i] = 0;
        g_dinv[i] = rsqrtf(g_deg[i]);
        if (i == 0) g_ptr[0] = 0;
    }
}

// 5) bucket fill: sorted-by-destination edge records {src, norm}
__global__ void k_fill(const float* __restrict__ w, int E) {
    int e = blockIdx.x * blockDim.x + threadIdx.x;
    if (e < E) {
        int r = g_rowi[e];
        int c = g_coli[e];
        float nrm = g_dinv[r] * w[e] * g_dinv[c];
        int pos = g_ptr[c] + atomicAdd(&g_cur[c], 1);
        g_rec[pos] = make_int2(r, __float_as_int(nrm));
    }
}

// ---------------------------------------------------------------------------
// 6) pull hop with SMEM record staging: block = 64 nodes x 5 threads.
//    Records for the block's node range are CONTIGUOUS in g_rec (dst-sorted);
//    one coalesced staging pass, then 5x per-node reuse hits SMEM not L2.
template <bool AtoB>
__global__ __launch_bounds__(HT)
void k_hop(int N) {
    __shared__ int2 srec[HCAP];
    const float4* __restrict__ src = AtoB ? g_bufA : g_bufB;
    float4*       __restrict__ dst = AtoB ? g_bufB : g_bufA;

    int tid  = threadIdx.x;
    int nb   = blockIdx.x * HNODES;
    int nEnd = nb + HNODES < N ? nb + HNODES : N;
    int beg  = g_ptr[nb];
    int end  = g_ptr[nEnd];
    int cnt  = end - beg;
    bool fits = (cnt <= HCAP);
    if (fits)
        for (int i = tid; i < cnt; i += HT) srec[i] = g_rec[beg + i];
    __syncthreads();

    int node = nb + tid / 5;
    if (node >= N) return;
    int ch = 2 * (tid % 5);

    float d  = g_dinv[node];
    float d2 = d * d;
    float4 s0 = src[(size_t)node * F4 + ch];
    float4 s1 = src[(size_t)node * F4 + ch + 1];
    float4 a0 = make_float4(d2 * s0.x, d2 * s0.y, d2 * s0.z, d2 * s0.w);
    float4 a1 = make_float4(d2 * s1.x, d2 * s1.y, d2 * s1.z, d2 * s1.w);

    int eb = g_ptr[node];
    int ee = g_ptr[node + 1];
    if (fits) {
        for (int e = eb - beg; e < ee - beg; e++) {
            int2  rec = srec[e];
            float nrm = __int_as_float(rec.y);
            const float4* vr = &src[(size_t)rec.x * F4 + ch];
            float4 v0 = vr[0];
            float4 v1 = vr[1];
            a0.x = fmaf(nrm, v0.x, a0.x);  a0.y = fmaf(nrm, v0.y, a0.y);
            a0.z = fmaf(nrm, v0.z, a0.z);  a0.w = fmaf(nrm, v0.w, a0.w);
            a1.x = fmaf(nrm, v1.x, a1.x);  a1.y = fmaf(nrm, v1.y, a1.y);
            a1.z = fmaf(nrm, v1.z, a1.z);  a1.w = fmaf(nrm, v1.w, a1.w);
        }
    } else {   // capacity fallback (statistically unreachable)
        for (int e = eb; e < ee; e++) {
            int2  rec = g_rec[e];
            float nrm = __int_as_float(rec.y);
            const float4* vr = &src[(size_t)rec.x * F4 + ch];
            float4 v0 = vr[0];
            float4 v1 = vr[1];
            a0.x = fmaf(nrm, v0.x, a0.x);  a0.y = fmaf(nrm, v0.y, a0.y);
            a0.z = fmaf(nrm, v0.z, a0.z);  a0.w = fmaf(nrm, v0.w, a0.w);
            a1.x = fmaf(nrm, v1.x, a1.x);  a1.y = fmaf(nrm, v1.y, a1.y);
            a1.z = fmaf(nrm, v1.z, a1.z);  a1.w = fmaf(nrm, v1.w, a1.w);
        }
    }
    dst[(size_t)node * F4 + ch]     = a0;
    dst[(size_t)node * F4 + ch + 1] = a1;
}

// ---------------------------------------------------------------------------
// 7) epilogue: out = log_softmax(relu(h + b))
__global__ void k_final(const float* __restrict__ b,
                        float* __restrict__ out, int N) {
    int n = blockIdx.x * blockDim.x + threadIdx.x;
    if (n >= N) return;

    float v[F_OUT];
    const float4* h = g_bufA + (size_t)n * F4;
#pragma unroll
    for (int c = 0; c < F4; c++) {
        float4 t = h[c];
        v[4*c+0] = t.x; v[4*c+1] = t.y; v[4*c+2] = t.z; v[4*c+3] = t.w;
    }
#pragma unroll
    for (int j = 0; j < F_OUT; j++)
        v[j] = fmaxf(v[j] + __ldg(&b[j]), 0.0f);

    float m = -1e30f;
#pragma unroll
    for (int j = 0; j < F_OUT; j++) m = fmaxf(m, v[j]);
    float s = 0.0f;
#pragma unroll
    for (int j = 0; j < F_OUT; j++) s += expf(v[j] - m);
    float lse = m + logf(s);

    float4* o = (float4*)out + (size_t)n * F4;
#pragma unroll
    for (int c = 0; c < F4; c++)
        o[c] = make_float4(v[4*c+0] - lse, v[4*c+1] - lse,
                           v[4*c+2] - lse, v[4*c+3] - lse);
}

// ---------------------------------------------------------------------------
extern "C" void kernel_launch(void* const* d_in, const int* in_sizes, int n_in,
                              void* d_out, int out_size) {
    const float* x   = (const float*)d_in[0];
    const void*  ei  = d_in[1];
    const float* w   = (const float*)d_in[2];
    const float* W   = (const float*)d_in[3];
    const float* b   = (const float*)d_in[4];
    float*       out = (float*)d_out;

    int N = in_sizes[0] / F_IN;   // 100000
    int E = in_sizes[2];          // 1600000

    const int T = 256;
    int gN  = (N + T - 1) / T;
    int gE  = (E + T - 1) / T;
    int gH  = (N + HNODES - 1) / HNODES;       // 1563
    int gG  = (N + NODES_PB - 1) / NODES_PB;   // 391
    int gW  = (F_IN * F_OUT + T - 1) / T;      // 40
    int nb  = (N + SCAN_BS - 1) / SCAN_BS;

    // ncu's fixed capture slot profiles my launch #3 -> GEMM goes there.
    k_init      <<<gN, T>>>(ei, N);          // 0
    k_prep_edges<<<gE, T>>>(ei, w, E, N);    // 1
    k_wt        <<<gW, T>>>(W);              // 2
    k_gemm      <<<gG, GT>>>(x, N);          // 3  <- profiled
    k_scanA     <<<nb, SCAN_BS>>>(N);        // 4
    k_scanB     <<<1, 128>>>(nb);            // 5
    k_scanC     <<<gN, T>>>(N);              // 6
    k_fill      <<<gE, T>>>(w, E);           // 7

    k_hop<true> <<<gH, HT>>>(N);             // 8
    k_hop<false><<<gH, HT>>>(N);             // 9

    k_final<<<gN, T>>>(b, out, N);           // 10
}